// round 13
// baseline (speedup 1.0000x reference)
#include <cuda_runtime.h>
#include <cuda_fp16.h>
#include <math.h>
#include <stdint.h>

#define BSZ   16
#define SEQ   4096
#define NST   256
#define HIN   128
#define HOUT  128
#define MTOT  (BSZ*SEQ)      // 65536
#define CHUNK 64
#define NCH   (SEQ/CHUNK)    // 64

// ------------------------------ scratch -----------------------------------
// g_bu: PACKED f16x2 (re,im) Bu per state, 4B each. Scan runs fp32 internally.
__device__ uint32_t g_bu[(size_t)MTOT*NST];
__device__ float2   g_part[BSZ*NCH*NST];
__device__ volatile int g_flag[BSZ*NCH];
__device__ uint32_t g_pre16[(size_t)MTOT*256];  // f16x2 pre-states
__device__ uint32_t g_u16[(size_t)MTOT*64];     // f16x2 u
__device__ uint32_t g_wbu16[512*64];            // f16x2 gamma*B (interleaved re/im rows)
__device__ uint32_t g_wy16[HOUT*320];           // f16x2 [Cre|-Cim interleave, D]

__device__ __forceinline__ uint32_t packf16(float v0, float v1) {
    uint32_t r;
    asm("cvt.rn.f16x2.f32 %0, %1, %2;" : "=r"(r) : "f"(v1), "f"(v0));
    return r;   // v0 in lower half
}
__device__ __forceinline__ float2 unpackf16(uint32_t v) {
    return __half22float2(*reinterpret_cast<__half2*>(&v));
}

#define MMA_F16(d, a, b0, b1)                                         \
    asm("mma.sync.aligned.m16n8k16.row.col.f32.f16.f16.f32 "          \
        "{%0,%1,%2,%3},{%4,%5,%6,%7},{%8,%9},{%0,%1,%2,%3};"          \
        : "+f"(d[0]), "+f"(d[1]), "+f"(d[2]), "+f"(d[3])              \
        : "r"(a[0]), "r"(a[1]), "r"(a[2]), "r"(a[3]), "r"(b0), "r"(b1))

#define LDSM4(r, addr)                                                \
    asm volatile("ldmatrix.sync.aligned.m8n8.x4.shared.b16 "          \
                 "{%0,%1,%2,%3}, [%4];"                               \
                 : "=r"((r)[0]), "=r"((r)[1]), "=r"((r)[2]), "=r"((r)[3]) \
                 : "r"(addr))

#define CP16(dst, src)                                                \
    asm volatile("cp.async.cg.shared.global [%0], [%1], 16;"          \
                 :: "r"(dst), "l"(src))
#define CP_COMMIT() asm volatile("cp.async.commit_group;" ::: "memory")

// smem: 2 buffers x 2 planes (A, W) x 128 rows x 20 words (80B stride,
// 16B-aligned, ldmatrix-conflict-free). Reused post-mainloop by the MODE0
// transpose epilogue (128 x 68 words = 8704 <= 10240).
#define CHW    16
#define RSTR   20
#define PLW    (128*RSTR)       // 2560 words/plane
#define BUFW   (2*PLW)          // 5120
#define SMEM_BYTES (2*BUFW*4)   // 40960 -> 2 CTAs/SM
#define TR     68               // transpose tile row stride (words)

// ---------------------------------------------------------------------------
#define NU (MTOT*64)
__global__ __launch_bounds__(256) void prep_all(
    const float* __restrict__ u,
    const float* __restrict__ Bre, const float* __restrict__ Bim,
    const float* __restrict__ gamma_log,
    const float* __restrict__ Cre, const float* __restrict__ Cim,
    const float* __restrict__ Dm)
{
    // clear lookback flags for this launch (graph-replay safe)
    if (blockIdx.x == 0) {
        for (int k = threadIdx.x; k < BSZ * NCH; k += 256) g_flag[k] = 0;
    }
    size_t i = (size_t)blockIdx.x * 256 + threadIdx.x;
    if (i < (size_t)NU) {
        float2 v = ((const float2*)u)[i];
        g_u16[i] = packf16(v.x, v.y);
    } else if (i < (size_t)NU + 512 * 64) {
        int t = (int)(i - NU);
        int n = t >> 6, j = t & 63;
        const float* B = (n & 1) ? Bim : Bre;
        float g = expf(gamma_log[n >> 1]);
        g_wbu16[t] = packf16(B[(n >> 1) * HIN + 2 * j] * g,
                             B[(n >> 1) * HIN + 2 * j + 1] * g);
    } else if (i < (size_t)NU + 512 * 64 + HOUT * 320) {
        int t = (int)(i - NU - 512 * 64);
        int o = t / 320, j = t % 320;
        float v0, v1;
        if (j < 256) { v0 = Cre[o * NST + j]; v1 = -Cim[o * NST + j]; }
        else { v0 = Dm[o * HIN + 2 * (j - 256)]; v1 = Dm[o * HIN + 2 * (j - 256) + 1]; }
        g_wy16[t] = packf16(v0, v1);
    }
}

// ---------------------------------------------------------------------------
// fp16 tensor-core GEMM: C[128m,128n] = A[128,K] x W[128n,K]^T, fp32 accum.
// MODE 0: A=u16 (K=128); W=wbu16 tile; out -> g_bu f16x2 packed, via smem
//         transpose for fully-coalesced 128B stores.
// MODE 1: A=[pre16|u16] (K=640); W=wy16; out -> y fp32 (stride 128).
// ---------------------------------------------------------------------------
template<int MODE>
__global__ __launch_bounds__(256, 2) void mma_gemm(float* __restrict__ y)
{
    extern __shared__ uint32_t sm[];
    uint32_t smb;
    asm("{ .reg .u64 t; cvta.to.shared.u64 t, %1; cvt.u32.u64 %0, t; }"
        : "=r"(smb) : "l"(sm));
    const int tid = threadIdx.x, lane = tid & 31, wid = tid >> 5;
    const int warp_m = (wid & 3) * 32, warp_n = (wid >> 2) * 64;
    const int ntile = (MODE == 0) ? blockIdx.x : 0;
    const int m0 = blockIdx.y * 128;
    const int NC = (MODE == 0) ? 4 : 20;

    float acc[2][8][4];
    #pragma unroll
    for (int f = 0; f < 2; f++)
        #pragma unroll
        for (int j = 0; j < 8; j++)
            #pragma unroll
            for (int q = 0; q < 4; q++) acc[f][j][q] = 0.f;

    auto cpy = [&](int c, int buf) {
        const uint32_t dbase = smb + (uint32_t)buf * BUFW * 4;
        if (tid < 128) {
            const int r = tid;
            const uint32_t* s;
            if (MODE == 0) {
                s = g_u16 + (size_t)(m0 + r) * 64 + c * CHW;
            } else if (c < 16) {
                s = g_pre16 + (size_t)(m0 + r) * 256 + c * CHW;
            } else {
                s = g_u16 + (size_t)(m0 + r) * 64 + (c - 16) * CHW;
            }
            uint32_t d0 = dbase + (r * RSTR) * 4;
            #pragma unroll
            for (int i = 0; i < 4; i++) CP16(d0 + i * 16, s + i * 4);
        } else {
            const int r = tid - 128;
            const uint32_t* s;
            if (MODE == 0) s = g_wbu16 + (size_t)(ntile * 128 + r) * 64 + c * CHW;
            else           s = g_wy16 + (size_t)r * 320 + c * CHW;
            uint32_t d1 = dbase + (PLW + r * RSTR) * 4;
            #pragma unroll
            for (int i = 0; i < 4; i++) CP16(d1 + i * 16, s + i * 4);
        }
    };

    const uint32_t a_off = (uint32_t)(warp_m + (lane & 15)) * (RSTR * 4)
                         + ((lane >> 4) * 16);
    const int bg = lane >> 3;
    const uint32_t b_off = (uint32_t)(warp_n + ((bg >> 1) * 8) + (lane & 7)) * (RSTR * 4)
                         + ((bg & 1) * 16) + PLW * 4;

    auto comp = [&](int buf) {
        const uint32_t bb = smb + (uint32_t)buf * BUFW * 4;
        #pragma unroll
        for (int ks = 0; ks < 2; ks++) {
            const uint32_t kb = ks * 32;
            uint32_t a[2][4];
            #pragma unroll
            for (int f = 0; f < 2; f++)
                LDSM4(a[f], bb + a_off + f * (16 * RSTR * 4) + kb);
            #pragma unroll
            for (int p = 0; p < 4; p++) {
                uint32_t b[4];
                LDSM4(b, bb + b_off + p * (16 * RSTR * 4) + kb);
                #pragma unroll
                for (int jj = 0; jj < 2; jj++) {
                    const int j = 2 * p + jj;
                    #pragma unroll
                    for (int f = 0; f < 2; f++)
                        MMA_F16(acc[f][j], a[f], b[2*jj], b[2*jj+1]);
                }
            }
        }
    };

    cpy(0, 0); CP_COMMIT();
    cpy(1, 1); CP_COMMIT();
    #pragma unroll 1
    for (int c = 0; c < NC; c++) {
        if (c + 1 < NC) asm volatile("cp.async.wait_group 1;" ::: "memory");
        else            asm volatile("cp.async.wait_group 0;" ::: "memory");
        __syncthreads();
        comp(c & 1);
        __syncthreads();
        if (c + 2 < NC) { cpy(c + 2, c & 1); CP_COMMIT(); }
    }

    if (MODE == 0) {
        // pack (re,im) pairs, transpose via smem, stream coalesced 256B rows
        #pragma unroll
        for (int f = 0; f < 2; f++) {
            const int ml = warp_m + f * 16 + (lane >> 2);
            #pragma unroll
            for (int j = 0; j < 8; j++) {
                const int col = (warp_n >> 1) + j * 4 + (lane & 3);
                sm[ml * TR + col]       = packf16(acc[f][j][0], acc[f][j][1]);
                sm[(ml + 8) * TR + col] = packf16(acc[f][j][2], acc[f][j][3]);
            }
        }
        __syncthreads();
        #pragma unroll
        for (int it = 0; it < 8; it++) {
            const int g = it * 256 + tid;
            const int row = g >> 4, c16 = g & 15;
            uint4 v = *(uint4*)&sm[row * TR + c16 * 4];
            *(uint4*)&g_bu[(size_t)(m0 + row) * 256 + ntile * 64 + c16 * 4] = v;
        }
    } else {
        #pragma unroll
        for (int f = 0; f < 2; f++) {
            const int m = m0 + warp_m + f * 16 + (lane >> 2);
            #pragma unroll
            for (int j = 0; j < 8; j++) {
                const int n = warp_n + j * 8 + (lane & 3) * 2;
                *(float2*)(y + (size_t)m * HOUT + n) =
                    make_float2(acc[f][j][0], acc[f][j][1]);
                *(float2*)(y + (size_t)(m + 8) * HOUT + n) =
                    make_float2(acc[f][j][2], acc[f][j][3]);
            }
        }
    }
}

// ---------------------------------------------------------------------------
// Single-pass scan with decoupled lookback. Block = (batch b, chunk c);
// thread n owns state n. Bu slice held in registers (one global read total).
//   1. local chunk reduce -> partial X_c
//   2. publish partial + flag (fence-protected)
//   3. wait for partials of chunks 0..c-1 (independent flags, no chain)
//   4. combine with lam^64 (same op order as the old phase2 -> identical bits)
//   5. replay from registers writing pre_t = x_{t-1} as f16x2
// ---------------------------------------------------------------------------
__device__ __forceinline__ void lam_of(const float* __restrict__ nu_log,
                                       const float* __restrict__ th_log,
                                       int n, float& lr, float& li) {
    float mod = expf(-expf(nu_log[n]));
    float th  = expf(th_log[n]);
    lr = mod * cosf(th);
    li = mod * sinf(th);
}

__global__ __launch_bounds__(256, 2) void scan_fused(
    const float* __restrict__ nu_log, const float* __restrict__ th_log)
{
    const int b = blockIdx.x >> 6, c = blockIdx.x & (NCH - 1);
    const int n = threadIdx.x;
    float lr, li; lam_of(nu_log, th_log, n, lr, li);
    const size_t base = ((size_t)b * SEQ + (size_t)c * CHUNK) * NST + n;

    // load the whole chunk slice into registers (64 x u32)
    uint32_t bu[CHUNK];
    #pragma unroll
    for (int i = 0; i < CHUNK; i++) bu[i] = g_bu[base + (size_t)i * NST];

    // 1. local reduce
    float xr = 0.f, xi = 0.f;
    #pragma unroll
    for (int i = 0; i < CHUNK; i++) {
        float2 v = unpackf16(bu[i]);
        float nxr = fmaf(lr, xr, fmaf(-li, xi, v.x));
        float nxi = fmaf(lr, xi, fmaf( li, xr, v.y));
        xr = nxr; xi = nxi;
    }

    // 2. publish
    volatile float2* part = (volatile float2*)g_part;
    const int pbase = b * NCH;
    part[(pbase + c) * NST + n].x = xr;
    part[(pbase + c) * NST + n].y = xi;
    __threadfence();
    __syncthreads();
    if (n == 0) g_flag[pbase + c] = 1;

    // 3+4. wait for predecessors, combine
    float sr = 0.f, si = 0.f;
    if (c > 0) {
        if (n < c) { while (g_flag[pbase + n] == 0) { __nanosleep(64); } }
        __syncthreads();
        float Lr = lr, Li = li;
        #pragma unroll
        for (int i = 0; i < 6; i++) {      // lam^64
            float a = Lr * Lr - Li * Li;
            float bq = 2.f * Lr * Li;
            Lr = a; Li = bq;
        }
        int k = 0;
        while (k < c) {
            float2 pb[16];
            const int cnt = (c - k < 16) ? (c - k) : 16;
            #pragma unroll 16
            for (int i = 0; i < cnt; i++) {
                pb[i].x = part[(pbase + k + i) * NST + n].x;
                pb[i].y = part[(pbase + k + i) * NST + n].y;
            }
            #pragma unroll 16
            for (int i = 0; i < cnt; i++) {
                float nsr = fmaf(Lr, sr, fmaf(-Li, si, pb[i].x));
                float nsi = fmaf(Lr, si, fmaf( Li, sr, pb[i].y));
                sr = nsr; si = nsi;
            }
            k += cnt;
        }
    }

    // 5. replay from registers; pre_t = x_{t-1}
    xr = sr; xi = si;
    #pragma unroll
    for (int i = 0; i < CHUNK; i++) {
        g_pre16[base + (size_t)i * NST] = packf16(xr, xi);
        float2 v = unpackf16(bu[i]);
        float nxr = fmaf(lr, xr, fmaf(-li, xi, v.x));
        float nxi = fmaf(lr, xi, fmaf( li, xr, v.y));
        xr = nxr; xi = nxi;
    }
}

// ================================ launch ===================================
extern "C" void kernel_launch(void* const* d_in, const int* in_sizes, int n_in,
                              void* d_out, int out_size) {
    const float* u         = (const float*)d_in[0];
    const float* nu_log    = (const float*)d_in[1];
    const float* theta_log = (const float*)d_in[2];
    const float* gamma_log = (const float*)d_in[3];
    const float* Bre       = (const float*)d_in[4];
    const float* Bim       = (const float*)d_in[5];
    const float* Cre       = (const float*)d_in[6];
    const float* Cim       = (const float*)d_in[7];
    const float* Dm        = (const float*)d_in[8];
    float* y = (float*)d_out;

    static int attr_done = 0;
    if (!attr_done) {
        cudaFuncSetAttribute(mma_gemm<0>,
                             cudaFuncAttributeMaxDynamicSharedMemorySize, SMEM_BYTES);
        cudaFuncSetAttribute(mma_gemm<1>,
                             cudaFuncAttributeMaxDynamicSharedMemorySize, SMEM_BYTES);
        attr_done = 1;
    }

    prep_all<<<(NU + 512 * 64 + HOUT * 320 + 255) / 256, 256>>>(
        u, Bre, Bim, gamma_log, Cre, Cim, Dm);

    dim3 gb(4, MTOT / 128);
    mma_gemm<0><<<gb, 256, SMEM_BYTES>>>(nullptr);

    scan_fused<<<BSZ * NCH, 256>>>(nu_log, theta_log);

    dim3 gy(1, MTOT / 128);
    mma_gemm<1><<<gy, 256, SMEM_BYTES>>>(y);
}

// round 14
// speedup vs baseline: 1.1687x; 1.1687x over previous
#include <cuda_runtime.h>
#include <cuda_fp16.h>
#include <math.h>
#include <stdint.h>

#define BSZ   16
#define SEQ   4096
#define NST   256
#define HIN   128
#define HOUT  128
#define MTOT  (BSZ*SEQ)      // 65536
#define CHUNK 64
#define NCH   (SEQ/CHUNK)    // 64

// ------------------------------ scratch -----------------------------------
// g_bu: PACKED f16x2 (re,im) Bu per state, 4B each. Scan runs fp32 internally.
__device__ uint32_t g_bu[(size_t)MTOT*NST];
__device__ float2   g_part[BSZ*NCH*NST];
__device__ uint32_t g_pre16[(size_t)MTOT*256];  // f16x2 pre-states
__device__ uint32_t g_u16[(size_t)MTOT*64];     // f16x2 u
__device__ uint32_t g_wbu16[512*64];            // f16x2 gamma*B (interleaved re/im rows)
__device__ uint32_t g_wy16[HOUT*320];           // f16x2 [Cre|-Cim interleave, D]

__device__ __forceinline__ uint32_t packf16(float v0, float v1) {
    uint32_t r;
    asm("cvt.rn.f16x2.f32 %0, %1, %2;" : "=r"(r) : "f"(v1), "f"(v0));
    return r;   // v0 in lower half
}
__device__ __forceinline__ float2 unpackf16(uint32_t v) {
    return __half22float2(*reinterpret_cast<__half2*>(&v));
}

#define MMA_F16(d, a, b0, b1)                                         \
    asm("mma.sync.aligned.m16n8k16.row.col.f32.f16.f16.f32 "          \
        "{%0,%1,%2,%3},{%4,%5,%6,%7},{%8,%9},{%0,%1,%2,%3};"          \
        : "+f"(d[0]), "+f"(d[1]), "+f"(d[2]), "+f"(d[3])              \
        : "r"(a[0]), "r"(a[1]), "r"(a[2]), "r"(a[3]), "r"(b0), "r"(b1))

#define LDSM4(r, addr)                                                \
    asm volatile("ldmatrix.sync.aligned.m8n8.x4.shared.b16 "          \
                 "{%0,%1,%2,%3}, [%4];"                               \
                 : "=r"((r)[0]), "=r"((r)[1]), "=r"((r)[2]), "=r"((r)[3]) \
                 : "r"(addr))

#define CP16(dst, src)                                                \
    asm volatile("cp.async.cg.shared.global [%0], [%1], 16;"          \
                 :: "r"(dst), "l"(src))
#define CP_COMMIT() asm volatile("cp.async.commit_group;" ::: "memory")

// smem: 3 buffers x 2 planes (A, W) x 128 rows x 20 words (80B stride,
// 16B-aligned, ldmatrix-conflict-free). Prefetch distance = 2 chunks.
// MODE0 transpose epilogue reuses the region (128 x 68 = 8704 <= 15360).
#define CHW    16
#define RSTR   20
#define PLW    (128*RSTR)       // 2560 words/plane
#define BUFW   (2*PLW)          // 5120
#define NSTG   3
#define SMEM_BYTES (NSTG*BUFW*4) // 61440 -> 2 CTAs/SM
#define TR     68               // transpose tile row stride (words)

// ---------------------------------------------------------------------------
#define NU (MTOT*64)
__global__ __launch_bounds__(256) void prep_all(
    const float* __restrict__ u,
    const float* __restrict__ Bre, const float* __restrict__ Bim,
    const float* __restrict__ gamma_log,
    const float* __restrict__ Cre, const float* __restrict__ Cim,
    const float* __restrict__ Dm)
{
    size_t i = (size_t)blockIdx.x * 256 + threadIdx.x;
    if (i < (size_t)NU) {
        float2 v = ((const float2*)u)[i];
        g_u16[i] = packf16(v.x, v.y);
    } else if (i < (size_t)NU + 512 * 64) {
        int t = (int)(i - NU);
        int n = t >> 6, j = t & 63;
        const float* B = (n & 1) ? Bim : Bre;
        float g = expf(gamma_log[n >> 1]);
        g_wbu16[t] = packf16(B[(n >> 1) * HIN + 2 * j] * g,
                             B[(n >> 1) * HIN + 2 * j + 1] * g);
    } else if (i < (size_t)NU + 512 * 64 + HOUT * 320) {
        int t = (int)(i - NU - 512 * 64);
        int o = t / 320, j = t % 320;
        float v0, v1;
        if (j < 256) { v0 = Cre[o * NST + j]; v1 = -Cim[o * NST + j]; }
        else { v0 = Dm[o * HIN + 2 * (j - 256)]; v1 = Dm[o * HIN + 2 * (j - 256) + 1]; }
        g_wy16[t] = packf16(v0, v1);
    }
}

// ---------------------------------------------------------------------------
// fp16 tensor-core GEMM: C[128m,128n] = A[128,K] x W[128n,K]^T, fp32 accum.
// 3-stage cp.async pipeline (prefetch distance 2).
// MODE 0: A=u16 (K=128, NC=4); W=wbu16 tile; out -> g_bu f16x2 via transpose.
// MODE 1: A=[pre16|u16] (K=640, NC=20); W=wy16; out -> y fp32.
// ---------------------------------------------------------------------------
template<int MODE>
__global__ __launch_bounds__(256, 2) void mma_gemm(float* __restrict__ y)
{
    extern __shared__ uint32_t sm[];
    uint32_t smb;
    asm("{ .reg .u64 t; cvta.to.shared.u64 t, %1; cvt.u32.u64 %0, t; }"
        : "=r"(smb) : "l"(sm));
    const int tid = threadIdx.x, lane = tid & 31, wid = tid >> 5;
    const int warp_m = (wid & 3) * 32, warp_n = (wid >> 2) * 64;
    const int ntile = (MODE == 0) ? blockIdx.x : 0;
    const int m0 = blockIdx.y * 128;
    const int NC = (MODE == 0) ? 4 : 20;

    float acc[2][8][4];
    #pragma unroll
    for (int f = 0; f < 2; f++)
        #pragma unroll
        for (int j = 0; j < 8; j++)
            #pragma unroll
            for (int q = 0; q < 4; q++) acc[f][j][q] = 0.f;

    auto cpy = [&](int c, int buf) {
        const uint32_t dbase = smb + (uint32_t)buf * BUFW * 4;
        if (tid < 128) {
            const int r = tid;
            const uint32_t* s;
            if (MODE == 0) {
                s = g_u16 + (size_t)(m0 + r) * 64 + c * CHW;
            } else if (c < 16) {
                s = g_pre16 + (size_t)(m0 + r) * 256 + c * CHW;
            } else {
                s = g_u16 + (size_t)(m0 + r) * 64 + (c - 16) * CHW;
            }
            uint32_t d0 = dbase + (r * RSTR) * 4;
            #pragma unroll
            for (int i = 0; i < 4; i++) CP16(d0 + i * 16, s + i * 4);
        } else {
            const int r = tid - 128;
            const uint32_t* s;
            if (MODE == 0) s = g_wbu16 + (size_t)(ntile * 128 + r) * 64 + c * CHW;
            else           s = g_wy16 + (size_t)r * 320 + c * CHW;
            uint32_t d1 = dbase + (PLW + r * RSTR) * 4;
            #pragma unroll
            for (int i = 0; i < 4; i++) CP16(d1 + i * 16, s + i * 4);
        }
    };

    const uint32_t a_off = (uint32_t)(warp_m + (lane & 15)) * (RSTR * 4)
                         + ((lane >> 4) * 16);
    const int bg = lane >> 3;
    const uint32_t b_off = (uint32_t)(warp_n + ((bg >> 1) * 8) + (lane & 7)) * (RSTR * 4)
                         + ((bg & 1) * 16) + PLW * 4;

    auto comp = [&](int buf) {
        const uint32_t bb = smb + (uint32_t)buf * BUFW * 4;
        #pragma unroll
        for (int ks = 0; ks < 2; ks++) {
            const uint32_t kb = ks * 32;
            uint32_t a[2][4];
            #pragma unroll
            for (int f = 0; f < 2; f++)
                LDSM4(a[f], bb + a_off + f * (16 * RSTR * 4) + kb);
            #pragma unroll
            for (int p = 0; p < 4; p++) {
                uint32_t b[4];
                LDSM4(b, bb + b_off + p * (16 * RSTR * 4) + kb);
                #pragma unroll
                for (int jj = 0; jj < 2; jj++) {
                    const int j = 2 * p + jj;
                    #pragma unroll
                    for (int f = 0; f < 2; f++)
                        MMA_F16(acc[f][j], a[f], b[2*jj], b[2*jj+1]);
                }
            }
        }
    };

    cpy(0, 0); CP_COMMIT();
    cpy(1, 1); CP_COMMIT();
    cpy(2, 2); CP_COMMIT();
    #pragma unroll 1
    for (int c = 0; c < NC; c++) {
        // ensure the group carrying chunk c has landed
        if (c <= NC - 3)      asm volatile("cp.async.wait_group 2;" ::: "memory");
        else if (c == NC - 2) asm volatile("cp.async.wait_group 1;" ::: "memory");
        else                  asm volatile("cp.async.wait_group 0;" ::: "memory");
        __syncthreads();
        comp(c % 3);
        __syncthreads();
        if (c + 3 < NC) { cpy(c + 3, c % 3); CP_COMMIT(); }
    }

    if (MODE == 0) {
        // pack (re,im) pairs, transpose via smem, stream coalesced 256B rows
        #pragma unroll
        for (int f = 0; f < 2; f++) {
            const int ml = warp_m + f * 16 + (lane >> 2);
            #pragma unroll
            for (int j = 0; j < 8; j++) {
                const int col = (warp_n >> 1) + j * 4 + (lane & 3);
                sm[ml * TR + col]       = packf16(acc[f][j][0], acc[f][j][1]);
                sm[(ml + 8) * TR + col] = packf16(acc[f][j][2], acc[f][j][3]);
            }
        }
        __syncthreads();
        #pragma unroll
        for (int it = 0; it < 8; it++) {
            const int g = it * 256 + tid;
            const int row = g >> 4, c16 = g & 15;
            uint4 v = *(uint4*)&sm[row * TR + c16 * 4];
            *(uint4*)&g_bu[(size_t)(m0 + row) * 256 + ntile * 64 + c16 * 4] = v;
        }
    } else {
        #pragma unroll
        for (int f = 0; f < 2; f++) {
            const int m = m0 + warp_m + f * 16 + (lane >> 2);
            #pragma unroll
            for (int j = 0; j < 8; j++) {
                const int n = warp_n + j * 8 + (lane & 3) * 2;
                *(float2*)(y + (size_t)m * HOUT + n) =
                    make_float2(acc[f][j][0], acc[f][j][1]);
                *(float2*)(y + (size_t)(m + 8) * HOUT + n) =
                    make_float2(acc[f][j][2], acc[f][j][3]);
            }
        }
    }
}

// ============================== scan kernels ===============================
__device__ __forceinline__ void lam_of(const float* __restrict__ nu_log,
                                       const float* __restrict__ th_log,
                                       int n, float& lr, float& li) {
    float mod = expf(-expf(nu_log[n]));
    float th  = expf(th_log[n]);
    lr = mod * cosf(th);
    li = mod * sinf(th);
}

__global__ __launch_bounds__(NST) void scan_phase1(
    const float* __restrict__ nu_log, const float* __restrict__ th_log)
{
    int b = blockIdx.x / (NCH - 1), c = blockIdx.x % (NCH - 1);
    int n = threadIdx.x;
    float lr, li; lam_of(nu_log, th_log, n, lr, li);
    float xr = 0.f, xi = 0.f;
    size_t base = ((size_t)b * SEQ + (size_t)c * CHUNK) * NST + n;
    uint32_t buf[16];
    #pragma unroll 1
    for (int g = 0; g < CHUNK / 16; g++) {
        #pragma unroll
        for (int i = 0; i < 16; i++)
            buf[i] = g_bu[base + (size_t)(g * 16 + i) * NST];
        #pragma unroll
        for (int i = 0; i < 16; i++) {
            float2 v = unpackf16(buf[i]);
            float nxr = fmaf(lr, xr, fmaf(-li, xi, v.x));
            float nxi = fmaf(lr, xi, fmaf( li, xr, v.y));
            xr = nxr; xi = nxi;
        }
    }
    g_part[(b * NCH + c) * NST + n] = make_float2(xr, xi);
}

__global__ __launch_bounds__(NST) void scan_phase2(
    const float* __restrict__ nu_log, const float* __restrict__ th_log)
{
    int b = blockIdx.x;
    int n = threadIdx.x;
    float lr, li; lam_of(nu_log, th_log, n, lr, li);
    float Lr = lr, Li = li;
    #pragma unroll
    for (int i = 0; i < 6; i++) {
        float nr = Lr * Lr - Li * Li;
        float ni = 2.f * Lr * Li;
        Lr = nr; Li = ni;
    }
    float sr = 0.f, si = 0.f;
    float2 buf[16];
    #pragma unroll 1
    for (int g = 0; g < NCH / 16; g++) {
        #pragma unroll
        for (int i = 0; i < 16; i++)
            buf[i] = g_part[(b * NCH + g * 16 + i) * NST + n];
        #pragma unroll
        for (int i = 0; i < 16; i++) {
            int idx = (b * NCH + g * 16 + i) * NST + n;
            g_part[idx] = make_float2(sr, si);
            float nsr = fmaf(Lr, sr, fmaf(-Li, si, buf[i].x));
            float nsi = fmaf(Lr, si, fmaf( Li, sr, buf[i].y));
            sr = nsr; si = nsi;
        }
    }
}

__global__ __launch_bounds__(NST) void scan_phase3(
    const float* __restrict__ nu_log, const float* __restrict__ th_log)
{
    int b = blockIdx.x / NCH, c = blockIdx.x % NCH;
    int n = threadIdx.x;
    float lr, li; lam_of(nu_log, th_log, n, lr, li);
    float2 s = g_part[(b * NCH + c) * NST + n];
    float xr = s.x, xi = s.y;
    size_t base = ((size_t)b * SEQ + (size_t)c * CHUNK) * NST + n;
    uint32_t buf[16];
    #pragma unroll 1
    for (int g = 0; g < CHUNK / 16; g++) {
        #pragma unroll
        for (int i = 0; i < 16; i++)
            buf[i] = g_bu[base + (size_t)(g * 16 + i) * NST];
        #pragma unroll
        for (int i = 0; i < 16; i++) {
            size_t off = base + (size_t)(g * 16 + i) * NST;
            g_pre16[off] = packf16(xr, xi);      // pre_t = x_{t-1}
            float2 v = unpackf16(buf[i]);
            float nxr = fmaf(lr, xr, fmaf(-li, xi, v.x));
            float nxi = fmaf(lr, xi, fmaf( li, xr, v.y));
            xr = nxr; xi = nxi;
        }
    }
}

// ================================ launch ===================================
extern "C" void kernel_launch(void* const* d_in, const int* in_sizes, int n_in,
                              void* d_out, int out_size) {
    const float* u         = (const float*)d_in[0];
    const float* nu_log    = (const float*)d_in[1];
    const float* theta_log = (const float*)d_in[2];
    const float* gamma_log = (const float*)d_in[3];
    const float* Bre       = (const float*)d_in[4];
    const float* Bim       = (const float*)d_in[5];
    const float* Cre       = (const float*)d_in[6];
    const float* Cim       = (const float*)d_in[7];
    const float* Dm        = (const float*)d_in[8];
    float* y = (float*)d_out;

    static int attr_done = 0;
    if (!attr_done) {
        cudaFuncSetAttribute(mma_gemm<0>,
                             cudaFuncAttributeMaxDynamicSharedMemorySize, SMEM_BYTES);
        cudaFuncSetAttribute(mma_gemm<1>,
                             cudaFuncAttributeMaxDynamicSharedMemorySize, SMEM_BYTES);
        attr_done = 1;
    }

    prep_all<<<(NU + 512 * 64 + HOUT * 320 + 255) / 256, 256>>>(
        u, Bre, Bim, gamma_log, Cre, Cim, Dm);

    dim3 gb(4, MTOT / 128);
    mma_gemm<0><<<gb, 256, SMEM_BYTES>>>(nullptr);

    scan_phase1<<<BSZ * (NCH - 1), NST>>>(nu_log, theta_log);
    scan_phase2<<<BSZ, NST>>>(nu_log, theta_log);
    scan_phase3<<<BSZ * NCH, NST>>>(nu_log, theta_log);

    dim3 gy(1, MTOT / 128);
    mma_gemm<1><<<gy, 256, SMEM_BYTES>>>(y);
}

// round 15
// speedup vs baseline: 1.1939x; 1.0215x over previous
#include <cuda_runtime.h>
#include <cuda_fp16.h>
#include <math.h>
#include <stdint.h>

#define BSZ   16
#define SEQ   4096
#define NST   256
#define HIN   128
#define HOUT  128
#define MTOT  (BSZ*SEQ)      // 65536
#define CHUNK 64
#define NCH   (SEQ/CHUNK)    // 64

// ------------------------------ scratch -----------------------------------
// g_bu: PACKED f16x2 (re,im) Bu per state, 4B each. Scan runs fp32 internally.
__device__ uint32_t g_bu[(size_t)MTOT*NST];
__device__ float2   g_part[BSZ*NCH*NST];
__device__ uint32_t g_pre16[(size_t)MTOT*256];  // f16x2 pre-states
__device__ uint32_t g_u16[(size_t)MTOT*64];     // f16x2 u
__device__ uint32_t g_wbu16[512*64];            // f16x2 gamma*B (interleaved re/im rows)
__device__ uint32_t g_wy16[HOUT*320];           // f16x2 [Cre|-Cim interleave, D]

__device__ __forceinline__ uint32_t packf16(float v0, float v1) {
    uint32_t r;
    asm("cvt.rn.f16x2.f32 %0, %1, %2;" : "=r"(r) : "f"(v1), "f"(v0));
    return r;   // v0 in lower half
}
__device__ __forceinline__ float2 unpackf16(uint32_t v) {
    return __half22float2(*reinterpret_cast<__half2*>(&v));
}

#define MMA_F16(d, a, b0, b1)                                         \
    asm("mma.sync.aligned.m16n8k16.row.col.f32.f16.f16.f32 "          \
        "{%0,%1,%2,%3},{%4,%5,%6,%7},{%8,%9},{%0,%1,%2,%3};"          \
        : "+f"(d[0]), "+f"(d[1]), "+f"(d[2]), "+f"(d[3])              \
        : "r"(a[0]), "r"(a[1]), "r"(a[2]), "r"(a[3]), "r"(b0), "r"(b1))

#define LDSM4(r, addr)                                                \
    asm volatile("ldmatrix.sync.aligned.m8n8.x4.shared.b16 "          \
                 "{%0,%1,%2,%3}, [%4];"                               \
                 : "=r"((r)[0]), "=r"((r)[1]), "=r"((r)[2]), "=r"((r)[3]) \
                 : "r"(addr))

#define CP16(dst, src)                                                \
    asm volatile("cp.async.cg.shared.global [%0], [%1], 16;"          \
                 :: "r"(dst), "l"(src))
#define CP_COMMIT() asm volatile("cp.async.commit_group;" ::: "memory")

// smem: 3 buffers x 2 planes (A, W) x 128 rows x 20 words (80B stride,
// 16B-aligned, ldmatrix-conflict-free). MODE0 transpose epilogue reuses the
// region (128 x 68 = 8704 <= 15360).
#define CHW    16
#define RSTR   20
#define PLW    (128*RSTR)       // 2560 words/plane
#define BUFW   (2*PLW)          // 5120
#define NSTG   3
#define SMEM_BYTES (NSTG*BUFW*4) // 61440 -> 2 CTAs/SM
#define TR     68               // transpose tile row stride (words)

// ---------------------------------------------------------------------------
#define NU (MTOT*64)
__global__ __launch_bounds__(256) void prep_all(
    const float* __restrict__ u,
    const float* __restrict__ Bre, const float* __restrict__ Bim,
    const float* __restrict__ gamma_log,
    const float* __restrict__ Cre, const float* __restrict__ Cim,
    const float* __restrict__ Dm)
{
    size_t i = (size_t)blockIdx.x * 256 + threadIdx.x;
    if (i < (size_t)NU) {
        float2 v = ((const float2*)u)[i];
        g_u16[i] = packf16(v.x, v.y);
    } else if (i < (size_t)NU + 512 * 64) {
        int t = (int)(i - NU);
        int n = t >> 6, j = t & 63;
        const float* B = (n & 1) ? Bim : Bre;
        float g = expf(gamma_log[n >> 1]);
        g_wbu16[t] = packf16(B[(n >> 1) * HIN + 2 * j] * g,
                             B[(n >> 1) * HIN + 2 * j + 1] * g);
    } else if (i < (size_t)NU + 512 * 64 + HOUT * 320) {
        int t = (int)(i - NU - 512 * 64);
        int o = t / 320, j = t % 320;
        float v0, v1;
        if (j < 256) { v0 = Cre[o * NST + j]; v1 = -Cim[o * NST + j]; }
        else { v0 = Dm[o * HIN + 2 * (j - 256)]; v1 = Dm[o * HIN + 2 * (j - 256) + 1]; }
        g_wy16[t] = packf16(v0, v1);
    }
}

// ---------------------------------------------------------------------------
// fp16 tensor-core GEMM: C[128m,128n] = A[128,K] x W[128n,K]^T, fp32 accum.
// 3-stage cp.async pipeline, ONE __syncthreads per chunk (CUTLASS multistage
// ordering: wait -> sync -> issue cpy(c+2) -> comp(c); the sync also guards
// buffer (c-1)%3 which cpy(c+2) overwrites).
// MODE 0: A=u16 (K=128, NC=4); W=wbu16 tile; out -> g_bu f16x2 via transpose.
// MODE 1: A=[pre16|u16] (K=640, NC=20); W=wy16; out -> y fp32.
// ---------------------------------------------------------------------------
template<int MODE>
__global__ __launch_bounds__(256, 2) void mma_gemm(float* __restrict__ y)
{
    extern __shared__ uint32_t sm[];
    uint32_t smb;
    asm("{ .reg .u64 t; cvta.to.shared.u64 t, %1; cvt.u32.u64 %0, t; }"
        : "=r"(smb) : "l"(sm));
    const int tid = threadIdx.x, lane = tid & 31, wid = tid >> 5;
    const int warp_m = (wid & 3) * 32, warp_n = (wid >> 2) * 64;
    const int ntile = (MODE == 0) ? blockIdx.x : 0;
    const int m0 = blockIdx.y * 128;
    const int NC = (MODE == 0) ? 4 : 20;

    float acc[2][8][4];
    #pragma unroll
    for (int f = 0; f < 2; f++)
        #pragma unroll
        for (int j = 0; j < 8; j++)
            #pragma unroll
            for (int q = 0; q < 4; q++) acc[f][j][q] = 0.f;

    auto cpy = [&](int c, int buf) {
        const uint32_t dbase = smb + (uint32_t)buf * BUFW * 4;
        if (tid < 128) {
            const int r = tid;
            const uint32_t* s;
            if (MODE == 0) {
                s = g_u16 + (size_t)(m0 + r) * 64 + c * CHW;
            } else if (c < 16) {
                s = g_pre16 + (size_t)(m0 + r) * 256 + c * CHW;
            } else {
                s = g_u16 + (size_t)(m0 + r) * 64 + (c - 16) * CHW;
            }
            uint32_t d0 = dbase + (r * RSTR) * 4;
            #pragma unroll
            for (int i = 0; i < 4; i++) CP16(d0 + i * 16, s + i * 4);
        } else {
            const int r = tid - 128;
            const uint32_t* s;
            if (MODE == 0) s = g_wbu16 + (size_t)(ntile * 128 + r) * 64 + c * CHW;
            else           s = g_wy16 + (size_t)r * 320 + c * CHW;
            uint32_t d1 = dbase + (PLW + r * RSTR) * 4;
            #pragma unroll
            for (int i = 0; i < 4; i++) CP16(d1 + i * 16, s + i * 4);
        }
    };

    const uint32_t a_off = (uint32_t)(warp_m + (lane & 15)) * (RSTR * 4)
                         + ((lane >> 4) * 16);
    const int bg = lane >> 3;
    const uint32_t b_off = (uint32_t)(warp_n + ((bg >> 1) * 8) + (lane & 7)) * (RSTR * 4)
                         + ((bg & 1) * 16) + PLW * 4;

    auto comp = [&](int buf) {
        const uint32_t bb = smb + (uint32_t)buf * BUFW * 4;
        #pragma unroll
        for (int ks = 0; ks < 2; ks++) {
            const uint32_t kb = ks * 32;
            uint32_t a[2][4];
            #pragma unroll
            for (int f = 0; f < 2; f++)
                LDSM4(a[f], bb + a_off + f * (16 * RSTR * 4) + kb);
            #pragma unroll
            for (int p = 0; p < 4; p++) {
                uint32_t b[4];
                LDSM4(b, bb + b_off + p * (16 * RSTR * 4) + kb);
                #pragma unroll
                for (int jj = 0; jj < 2; jj++) {
                    const int j = 2 * p + jj;
                    #pragma unroll
                    for (int f = 0; f < 2; f++)
                        MMA_F16(acc[f][j], a[f], b[2*jj], b[2*jj+1]);
                }
            }
        }
    };

    cpy(0, 0); CP_COMMIT();
    cpy(1, 1); CP_COMMIT();
    #pragma unroll 1
    for (int c = 0; c < NC; c++) {
        if (c + 1 < NC) asm volatile("cp.async.wait_group 1;" ::: "memory");
        else            asm volatile("cp.async.wait_group 0;" ::: "memory");
        __syncthreads();
        if (c + 2 < NC) { cpy(c + 2, (c + 2) % NSTG); CP_COMMIT(); }
        comp(c % NSTG);
    }

    if (MODE == 0) {
        // pack (re,im) pairs, transpose via smem, stream coalesced 256B rows
        __syncthreads();   // all comp reads done before overwriting smem
        #pragma unroll
        for (int f = 0; f < 2; f++) {
            const int ml = warp_m + f * 16 + (lane >> 2);
            #pragma unroll
            for (int j = 0; j < 8; j++) {
                const int col = (warp_n >> 1) + j * 4 + (lane & 3);
                sm[ml * TR + col]       = packf16(acc[f][j][0], acc[f][j][1]);
                sm[(ml + 8) * TR + col] = packf16(acc[f][j][2], acc[f][j][3]);
            }
        }
        __syncthreads();
        #pragma unroll
        for (int it = 0; it < 8; it++) {
            const int g = it * 256 + tid;
            const int row = g >> 4, c16 = g & 15;
            uint4 v = *(uint4*)&sm[row * TR + c16 * 4];
            *(uint4*)&g_bu[(size_t)(m0 + row) * 256 + ntile * 64 + c16 * 4] = v;
        }
    } else {
        #pragma unroll
        for (int f = 0; f < 2; f++) {
            const int m = m0 + warp_m + f * 16 + (lane >> 2);
            #pragma unroll
            for (int j = 0; j < 8; j++) {
                const int n = warp_n + j * 8 + (lane & 3) * 2;
                *(float2*)(y + (size_t)m * HOUT + n) =
                    make_float2(acc[f][j][0], acc[f][j][1]);
                *(float2*)(y + (size_t)(m + 8) * HOUT + n) =
                    make_float2(acc[f][j][2], acc[f][j][3]);
            }
        }
    }
}

// ============================== scan kernels ===============================
__device__ __forceinline__ void lam_of(const float* __restrict__ nu_log,
                                       const float* __restrict__ th_log,
                                       int n, float& lr, float& li) {
    float mod = expf(-expf(nu_log[n]));
    float th  = expf(th_log[n]);
    lr = mod * cosf(th);
    li = mod * sinf(th);
}

__global__ __launch_bounds__(NST) void scan_phase1(
    const float* __restrict__ nu_log, const float* __restrict__ th_log)
{
    int b = blockIdx.x / (NCH - 1), c = blockIdx.x % (NCH - 1);
    int n = threadIdx.x;
    float lr, li; lam_of(nu_log, th_log, n, lr, li);
    float xr = 0.f, xi = 0.f;
    size_t base = ((size_t)b * SEQ + (size_t)c * CHUNK) * NST + n;
    uint32_t buf[16];
    #pragma unroll 1
    for (int g = 0; g < CHUNK / 16; g++) {
        #pragma unroll
        for (int i = 0; i < 16; i++)
            buf[i] = g_bu[base + (size_t)(g * 16 + i) * NST];
        #pragma unroll
        for (int i = 0; i < 16; i++) {
            float2 v = unpackf16(buf[i]);
            float nxr = fmaf(lr, xr, fmaf(-li, xi, v.x));
            float nxi = fmaf(lr, xi, fmaf( li, xr, v.y));
            xr = nxr; xi = nxi;
        }
    }
    g_part[(b * NCH + c) * NST + n] = make_float2(xr, xi);
}

__global__ __launch_bounds__(NST) void scan_phase2(
    const float* __restrict__ nu_log, const float* __restrict__ th_log)
{
    int b = blockIdx.x;
    int n = threadIdx.x;
    float lr, li; lam_of(nu_log, th_log, n, lr, li);
    float Lr = lr, Li = li;
    #pragma unroll
    for (int i = 0; i < 6; i++) {
        float nr = Lr * Lr - Li * Li;
        float ni = 2.f * Lr * Li;
        Lr = nr; Li = ni;
    }
    float sr = 0.f, si = 0.f;
    float2 buf[16];
    #pragma unroll 1
    for (int g = 0; g < NCH / 16; g++) {
        #pragma unroll
        for (int i = 0; i < 16; i++)
            buf[i] = g_part[(b * NCH + g * 16 + i) * NST + n];
        #pragma unroll
        for (int i = 0; i < 16; i++) {
            int idx = (b * NCH + g * 16 + i) * NST + n;
            g_part[idx] = make_float2(sr, si);
            float nsr = fmaf(Lr, sr, fmaf(-Li, si, buf[i].x));
            float nsi = fmaf(Lr, si, fmaf( Li, sr, buf[i].y));
            sr = nsr; si = nsi;
        }
    }
}

__global__ __launch_bounds__(NST) void scan_phase3(
    const float* __restrict__ nu_log, const float* __restrict__ th_log)
{
    int b = blockIdx.x / NCH, c = blockIdx.x % NCH;
    int n = threadIdx.x;
    float lr, li; lam_of(nu_log, th_log, n, lr, li);
    float2 s = g_part[(b * NCH + c) * NST + n];
    float xr = s.x, xi = s.y;
    size_t base = ((size_t)b * SEQ + (size_t)c * CHUNK) * NST + n;
    uint32_t buf[16];
    #pragma unroll 1
    for (int g = 0; g < CHUNK / 16; g++) {
        #pragma unroll
        for (int i = 0; i < 16; i++)
            buf[i] = g_bu[base + (size_t)(g * 16 + i) * NST];
        #pragma unroll
        for (int i = 0; i < 16; i++) {
            size_t off = base + (size_t)(g * 16 + i) * NST;
            g_pre16[off] = packf16(xr, xi);      // pre_t = x_{t-1}
            float2 v = unpackf16(buf[i]);
            float nxr = fmaf(lr, xr, fmaf(-li, xi, v.x));
            float nxi = fmaf(lr, xi, fmaf( li, xr, v.y));
            xr = nxr; xi = nxi;
        }
    }
}

// ================================ launch ===================================
extern "C" void kernel_launch(void* const* d_in, const int* in_sizes, int n_in,
                              void* d_out, int out_size) {
    const float* u         = (const float*)d_in[0];
    const float* nu_log    = (const float*)d_in[1];
    const float* theta_log = (const float*)d_in[2];
    const float* gamma_log = (const float*)d_in[3];
    const float* Bre       = (const float*)d_in[4];
    const float* Bim       = (const float*)d_in[5];
    const float* Cre       = (const float*)d_in[6];
    const float* Cim       = (const float*)d_in[7];
    const float* Dm        = (const float*)d_in[8];
    float* y = (float*)d_out;

    static int attr_done = 0;
    if (!attr_done) {
        cudaFuncSetAttribute(mma_gemm<0>,
                             cudaFuncAttributeMaxDynamicSharedMemorySize, SMEM_BYTES);
        cudaFuncSetAttribute(mma_gemm<1>,
                             cudaFuncAttributeMaxDynamicSharedMemorySize, SMEM_BYTES);
        attr_done = 1;
    }

    prep_all<<<(NU + 512 * 64 + HOUT * 320 + 255) / 256, 256>>>(
        u, Bre, Bim, gamma_log, Cre, Cim, Dm);

    dim3 gb(4, MTOT / 128);
    mma_gemm<0><<<gb, 256, SMEM_BYTES>>>(nullptr);

    scan_phase1<<<BSZ * (NCH - 1), NST>>>(nu_log, theta_log);
    scan_phase2<<<BSZ, NST>>>(nu_log, theta_log);
    scan_phase3<<<BSZ * NCH, NST>>>(nu_log, theta_log);

    dim3 gy(1, MTOT / 128);
    mma_gemm<1><<<gy, 256, SMEM_BYTES>>>(y);
}